// round 1
// baseline (speedup 1.0000x reference)
#include <cuda_runtime.h>
#include <stdint.h>

// Problem constants (fixed shapes from reference)
#define HW      262144      // 512*512
#define NBINS   65536       // 16-bit key histogram
#define CAP     8192        // candidate capacity per side (power of 2 for bitonic)
#define Z_MAX   2000
#define NTHR    200         // thresholds 10,20,...,2000

__device__ unsigned int       g_hist[NBINS];
__device__ unsigned long long g_bot_keys[CAP];
__device__ unsigned long long g_top_keys[CAP];
__device__ float              g_bot_pay[CAP];   // backg = 1 - forg
__device__ float              g_top_pay[CAP];   // forg
__device__ unsigned int       g_bot_cnt;
__device__ unsigned int       g_top_cnt;
__device__ unsigned int       g_lo_bin;         // bin containing the Z_MAX-th smallest
__device__ unsigned int       g_hi_bin;         // bin containing the Z_MAX-th largest

// Monotonic float -> uint32 mapping (ascending order preserved)
__device__ __forceinline__ unsigned int fkey(float x) {
    unsigned int u = __float_as_uint(x);
    return (u & 0x80000000u) ? ~u : (u | 0x80000000u);
}

__global__ void k_init() {
    int i = blockIdx.x * blockDim.x + threadIdx.x;
    int n = gridDim.x * blockDim.x;
    for (int b = i; b < NBINS; b += n) g_hist[b] = 0u;
    for (int b = i; b < CAP; b += n) {
        g_bot_keys[b] = 0xFFFFFFFFFFFFFFFFull; // pads sort to the end (ascending)
        g_top_keys[b] = 0ull;                  // pads sort to the front
        g_bot_pay[b]  = 0.0f;
        g_top_pay[b]  = 0.0f;
    }
    if (i == 0) { g_bot_cnt = 0u; g_top_cnt = 0u; }
}

__global__ void k_hist(const float* __restrict__ cam) {
    int i = blockIdx.x * blockDim.x + threadIdx.x;
    if (i < HW) atomicAdd(&g_hist[fkey(cam[i]) >> 16], 1u);
}

// One block, 256 threads: each owns 256 contiguous bins.
// Finds lo_bin = min bin with prefix count >= Z_MAX,
//       hi_bin = max bin with suffix count >= Z_MAX.
__global__ void k_select() {
    __shared__ unsigned int chunk[256];
    __shared__ unsigned int csum[257];
    int t = threadIdx.x;
    unsigned int s = 0;
    int base = t * 256;
    for (int b = base; b < base + 256; b++) s += g_hist[b];
    chunk[t] = s;
    __syncthreads();
    if (t == 0) {
        unsigned int acc = 0;
        for (int i = 0; i < 256; i++) { csum[i] = acc; acc += chunk[i]; }
        csum[256] = acc;
    }
    __syncthreads();

    const unsigned int Z = Z_MAX;
    // bottom cutoff
    unsigned int pre = csum[t];
    if (pre < Z && pre + chunk[t] >= Z) {
        unsigned int acc = pre;
        for (int b = base; b < base + 256; b++) {
            acc += g_hist[b];
            if (acc >= Z) { g_lo_bin = (unsigned int)b; break; }
        }
    }
    // top cutoff
    unsigned int total     = csum[256];
    unsigned int suf_after = total - (csum[t] + chunk[t]);
    if (suf_after < Z && suf_after + chunk[t] >= Z) {
        unsigned int acc = suf_after;
        for (int b = base + 255; b >= base; b--) {
            acc += g_hist[b];
            if (acc >= Z) { g_hi_bin = (unsigned int)b; break; }
        }
    }
}

__global__ void k_gather(const float* __restrict__ cam,
                         const float* __restrict__ mask) {
    int i = blockIdx.x * blockDim.x + threadIdx.x;
    if (i >= HW) return;
    unsigned int uk  = fkey(cam[i]);
    unsigned int bin = uk >> 16;
    unsigned int lo  = g_lo_bin;
    unsigned int hi  = g_hi_bin;
    if (bin <= lo) {
        unsigned int p = atomicAdd(&g_bot_cnt, 1u);
        if (p < CAP) {
            g_bot_keys[p] = ((unsigned long long)uk << 32) | (unsigned int)i;
            g_bot_pay[p]  = 1.0f - mask[i];
        }
    }
    if (bin >= hi) {
        unsigned int p = atomicAdd(&g_top_cnt, 1u);
        if (p < CAP) {
            g_top_keys[p] = ((unsigned long long)uk << 32) | (unsigned int)i;
            g_top_pay[p]  = mask[i];
        }
    }
}

// grid = 2 blocks: block 0 -> bottom/acc_backg, block 1 -> top/acc_forg.
// Bitonic sort CAP (key64 ascending, payload carried), then serial prefix.
__global__ void k_sort_out(float* __restrict__ out) {
    extern __shared__ unsigned char sm[];
    unsigned long long* k = (unsigned long long*)sm;
    float* v = (float*)(sm + CAP * sizeof(unsigned long long));

    const bool top = (blockIdx.x == 1);
    const unsigned long long* gk = top ? g_top_keys : g_bot_keys;
    const float*              gv = top ? g_top_pay  : g_bot_pay;

    for (int i = threadIdx.x; i < CAP; i += blockDim.x) {
        k[i] = gk[i];
        v[i] = gv[i];
    }
    __syncthreads();

    for (int kk = 2; kk <= CAP; kk <<= 1) {
        for (int j = kk >> 1; j > 0; j >>= 1) {
            for (int i = threadIdx.x; i < CAP; i += blockDim.x) {
                int p = i ^ j;
                if (p > i) {
                    bool up = ((i & kk) == 0);
                    unsigned long long a = k[i], b = k[p];
                    bool sw = up ? (a > b) : (a < b);
                    if (sw) {
                        k[i] = b; k[p] = a;
                        float tv = v[i]; v[i] = v[p]; v[p] = tv;
                    }
                }
            }
            __syncthreads();
        }
    }

    if (threadIdx.x == 0) {
        float acc = 0.0f;
        for (int j = 0; j < Z_MAX; j++) {
            acc += top ? v[CAP - 1 - j] : v[j];
            int z = j + 1;
            if ((z % 10) == 0) {
                int ti = z / 10 - 1;                     // 0..199
                // out[0..199]   = acc_forg  (top)
                // out[200..399] = acc_backg (bottom)
                out[(top ? 0 : NTHR) + ti] = 100.0f * acc / (float)z;
            }
        }
    }
}

extern "C" void kernel_launch(void* const* d_in, const int* in_sizes, int n_in,
                              void* d_out, int out_size) {
    const float* cam  = (const float*)d_in[0];
    const float* mask = (const float*)d_in[1];
    float* out = (float*)d_out;

    static bool attr_set = false;
    if (!attr_set) {
        cudaFuncSetAttribute(k_sort_out,
                             cudaFuncAttributeMaxDynamicSharedMemorySize,
                             CAP * (sizeof(unsigned long long) + sizeof(float)));
        attr_set = true;
    }

    k_init<<<256, 256>>>();
    k_hist<<<(HW + 255) / 256, 256>>>(cam);
    k_select<<<1, 256>>>();
    k_gather<<<(HW + 255) / 256, 256>>>(cam, mask);
    k_sort_out<<<2, 512, CAP * (sizeof(unsigned long long) + sizeof(float))>>>(out);
}

// round 2
// speedup vs baseline: 4.0073x; 4.0073x over previous
#include <cuda_runtime.h>
#include <stdint.h>

#define HW      262144      // 512*512
#define NBINS   65536       // 16-bit key histogram
#define CAP     4096        // candidate capacity per side
#define Z_MAX   2000
#define NTHR    200
#define NSCAN   2048        // scan width (pow2 >= Z_MAX)

#define TPC     8           // threads per candidate in rank kernel
#define RBLK    256         // rank block size
#define CPB     (RBLK/TPC)  // candidates per rank block = 32

__device__ unsigned int       g_hist[NBINS];
__device__ unsigned long long g_keys[2][CAP];   // [0]=bottom, [1]=top
__device__ float              g_pay[2][CAP];    // [0]=1-mask, [1]=mask
__device__ unsigned int       g_cnt[2];
__device__ unsigned int       g_lo_bin;
__device__ unsigned int       g_hi_bin;
__device__ float              g_pre[2][NSCAN];  // payload placed at its rank

// Monotonic float -> uint32 (ascending order preserved)
__device__ __forceinline__ unsigned int fkey(float x) {
    unsigned int u = __float_as_uint(x);
    return (u & 0x80000000u) ? ~u : (u | 0x80000000u);
}

__global__ void k_init() {
    int i = blockIdx.x * blockDim.x + threadIdx.x;
    int n = gridDim.x * blockDim.x;
    for (int b = i; b < NBINS; b += n) g_hist[b] = 0u;
    for (int b = i; b < NSCAN; b += n) { g_pre[0][b] = 0.0f; g_pre[1][b] = 0.0f; }
    if (i == 0) { g_cnt[0] = 0u; g_cnt[1] = 0u; }
}

__global__ void k_hist(const float* __restrict__ cam) {
    int i = blockIdx.x * blockDim.x + threadIdx.x;
    if (i * 4 < HW) {
        float4 c = ((const float4*)cam)[i];
        atomicAdd(&g_hist[fkey(c.x) >> 16], 1u);
        atomicAdd(&g_hist[fkey(c.y) >> 16], 1u);
        atomicAdd(&g_hist[fkey(c.z) >> 16], 1u);
        atomicAdd(&g_hist[fkey(c.w) >> 16], 1u);
    }
}

// One block, 256 threads. Chunk sums via vector loads (high MLP),
// cutoff-chunk refinement done from SMEM (no dependent global-load chains).
__global__ void k_select() {
    __shared__ unsigned int chunk[256];
    __shared__ unsigned int csum[257];
    __shared__ int s_lo_c, s_hi_c;
    __shared__ unsigned int binbuf[256];
    int t = threadIdx.x;

    const uint4* h4 = (const uint4*)g_hist;   // 16384 uint4
    unsigned int s = 0;
    int b4 = t * 64;                          // 64 uint4 = 256 bins per thread
    #pragma unroll 8
    for (int i = 0; i < 64; i++) {
        uint4 q = h4[b4 + i];
        s += q.x + q.y + q.z + q.w;
    }
    chunk[t] = s;
    __syncthreads();
    if (t == 0) {
        unsigned int acc = 0;
        for (int i = 0; i < 256; i++) { csum[i] = acc; acc += chunk[i]; }
        csum[256] = acc;
    }
    __syncthreads();

    const unsigned int Z = Z_MAX;
    unsigned int total = csum[256];
    if (csum[t] < Z && csum[t] + chunk[t] >= Z) s_lo_c = t;
    if ((total - csum[t + 1]) < Z && (total - csum[t]) >= Z) s_hi_c = t;
    __syncthreads();

    // lo chunk refinement (in smem)
    binbuf[t] = g_hist[s_lo_c * 256 + t];
    __syncthreads();
    if (t == 0) {
        unsigned int acc = csum[s_lo_c];
        for (int b = 0; b < 256; b++) {
            acc += binbuf[b];
            if (acc >= Z) { g_lo_bin = (unsigned int)(s_lo_c * 256 + b); break; }
        }
    }
    __syncthreads();
    // hi chunk refinement
    binbuf[t] = g_hist[s_hi_c * 256 + t];
    __syncthreads();
    if (t == 0) {
        unsigned int acc = total - csum[s_hi_c + 1];
        for (int b = 255; b >= 0; b--) {
            acc += binbuf[b];
            if (acc >= Z) { g_hi_bin = (unsigned int)(s_hi_c * 256 + b); break; }
        }
    }
}

__global__ void k_gather(const float* __restrict__ cam,
                         const float* __restrict__ mask) {
    int i = blockIdx.x * blockDim.x + threadIdx.x;
    if (i >= HW) return;
    unsigned int uk  = fkey(cam[i]);
    unsigned int bin = uk >> 16;
    unsigned int lo  = g_lo_bin;
    unsigned int hi  = g_hi_bin;
    if (bin <= lo) {
        unsigned int p = atomicAdd(&g_cnt[0], 1u);
        if (p < CAP) {
            g_keys[0][p] = ((unsigned long long)uk << 32) | (unsigned int)i;
            g_pay[0][p]  = 1.0f - mask[i];
        }
    }
    if (bin >= hi) {
        unsigned int p = atomicAdd(&g_cnt[1], 1u);
        if (p < CAP) {
            g_keys[1][p] = ((unsigned long long)uk << 32) | (unsigned int)i;
            g_pay[1][p]  = mask[i];
        }
    }
}

// Pairwise ranking. grid = (CAP/CPB, 2). 8 lanes cooperate per candidate.
// side 0 (bottom): rank ascending. side 1 (top): rank descending.
__global__ void k_rank() {
    __shared__ unsigned long long sk[CAP];
    int side = blockIdx.y;
    unsigned int n = min(g_cnt[side], (unsigned int)CAP);

    int cand = blockIdx.x * CPB + threadIdx.x / TPC;
    if (blockIdx.x * CPB >= (int)n) return;   // whole block idle

    const unsigned long long* gk = g_keys[side];
    for (unsigned int i = threadIdx.x; i < n; i += RBLK) sk[i] = gk[i];
    __syncthreads();

    if (cand < (int)n) {
        int lane = threadIdx.x & (TPC - 1);
        unsigned long long ki = sk[cand];
        unsigned int cnt = 0;
        if (side) {
            for (unsigned int j = lane; j < n; j += TPC) cnt += (sk[j] > ki);
        } else {
            for (unsigned int j = lane; j < n; j += TPC) cnt += (sk[j] < ki);
        }
        cnt += __shfl_down_sync(0xffffffffu, cnt, 4, TPC);
        cnt += __shfl_down_sync(0xffffffffu, cnt, 2, TPC);
        cnt += __shfl_down_sync(0xffffffffu, cnt, 1, TPC);
        if (lane == 0 && cnt < Z_MAX) g_pre[side][cnt] = g_pay[side][cand];
    }
}

// grid = 2 blocks (one per side), 1024 threads. Hillis-Steele scan + outputs.
__global__ void k_out(float* __restrict__ out) {
    __shared__ float A[NSCAN];
    __shared__ float B[NSCAN];
    int side = blockIdx.x;
    int t = threadIdx.x;

    A[t]        = g_pre[side][t];
    A[t + 1024] = g_pre[side][t + 1024];
    __syncthreads();

    float* src = A;
    float* dst = B;
    #pragma unroll
    for (int off = 1; off < NSCAN; off <<= 1) {
        for (int i = t; i < NSCAN; i += 1024) {
            float v = src[i];
            if (i >= off) v += src[i - off];
            dst[i] = v;
        }
        __syncthreads();
        float* tmp = src; src = dst; dst = tmp;
    }

    if (t < NTHR) {
        int z = (t + 1) * 10;
        // out[0..199] = acc_forg (top, side 1); out[200..399] = acc_backg (bottom, side 0)
        out[(side ? 0 : NTHR) + t] = 100.0f * src[z - 1] / (float)z;
    }
}

extern "C" void kernel_launch(void* const* d_in, const int* in_sizes, int n_in,
                              void* d_out, int out_size) {
    const float* cam  = (const float*)d_in[0];
    const float* mask = (const float*)d_in[1];
    float* out = (float*)d_out;

    k_init<<<128, 256>>>();
    k_hist<<<(HW / 4 + 255) / 256, 256>>>(cam);
    k_select<<<1, 256>>>();
    k_gather<<<(HW + 255) / 256, 256>>>(cam, mask);
    dim3 rgrid(CAP / CPB, 2);
    k_rank<<<rgrid, RBLK>>>();
    k_out<<<2, 1024>>>(out);
}